// round 1
// baseline (speedup 1.0000x reference)
#include <cuda_runtime.h>

// Problem constants (fixed by the reference setup_inputs)
#define B_   8
#define N_   256
#define D_   16
#define KP1_ 4
#define REL_ 6
#define OUT_ 3

// Inputs (metadata order): As (ignored), Xs (B,N,D,K+1) f32, W (D*(K+1), 3) f32
// Output: actions (B, N, 3) f32
//
// Math (A = J - I fully connected, N=256):
//   L = J - N I,  L^2 = N^2 I - N J,  A^2 = (N-2) J + I
//   T_k[b,d] = sum_j Xs[b,j,d,k]
//   Zagg[b,i,d,0] = (d>=REL) ? X0 : 0
//   Zagg[b,i,d,1] = rel ? T1 - N X1            : T1 - X1
//   Zagg[b,i,d,2] = rel ? N X2 - T2 - (N-1) X1 : (N-2) T2 + X2
//   Zagg[b,i,d,3] = rel ? N T3 - N^2 X3 - (N-1) X1 : (N^2-3N+3) T3 - X3
//   actions = Zagg @ W, NaN -> 0

__global__ __launch_bounds__(N_) void reynolds_kernel(
    const float* __restrict__ Xs,   // (B, N, D, 4)
    const float* __restrict__ W,    // (64, 3)
    float* __restrict__ out)        // (B, N, 3)
{
    const int b   = blockIdx.x;
    const int i   = threadIdx.x;      // node index 0..255
    const int lane = i & 31;

    __shared__ float T[D_][KP1_];     // column sums T_k[d] (k=1..3 used)
    __shared__ float Ws[D_ * KP1_ * OUT_]; // 192 floats

    // init shared
    if (i < D_ * KP1_) ((float*)T)[i] = 0.0f;
    if (i < D_ * KP1_ * OUT_) Ws[i] = W[i];
    __syncthreads();

    // Each thread owns row i: 16 contiguous float4 (d-major, k in lanes)
    const float4* xrow = reinterpret_cast<const float4*>(
        Xs + (size_t)((b * N_ + i) * D_) * KP1_);
    float4 x[D_];
#pragma unroll
    for (int d = 0; d < D_; d++) x[d] = xrow[d];

    // Column-sum reduction: warp butterfly then one shared atomic per warp
#pragma unroll
    for (int d = 0; d < D_; d++) {
        float s1 = x[d].y, s2 = x[d].z, s3 = x[d].w;
#pragma unroll
        for (int off = 16; off; off >>= 1) {
            s1 += __shfl_xor_sync(0xffffffffu, s1, off);
            s2 += __shfl_xor_sync(0xffffffffu, s2, off);
            s3 += __shfl_xor_sync(0xffffffffu, s3, off);
        }
        if (lane == 0) {
            atomicAdd(&T[d][1], s1);
            atomicAdd(&T[d][2], s2);
            atomicAdd(&T[d][3], s3);
        }
    }
    __syncthreads();

    const float Nf  = 256.0f;
    const float N2f = 65536.0f;
    const float Nm1 = 255.0f;
    const float Nm2 = 254.0f;
    const float C3  = 64771.0f;  // N^2 - 3N + 3

    float acc0 = 0.0f, acc1 = 0.0f, acc2 = 0.0f;

#pragma unroll
    for (int d = 0; d < D_; d++) {
        const bool rel = (d < REL_);
        const float X0 = x[d].x, X1 = x[d].y, X2 = x[d].z, X3 = x[d].w;
        const float t1 = T[d][1], t2 = T[d][2], t3 = T[d][3];

        const float z0 = rel ? 0.0f : X0;
        const float z1 = rel ? (t1 - Nf * X1)
                             : (t1 - X1);
        const float z2 = rel ? (Nf * X2 - t2 - Nm1 * X1)
                             : (Nm2 * t2 + X2);
        const float z3 = rel ? (Nf * t3 - N2f * X3 - Nm1 * X1)
                             : (C3 * t3 - X3);

        const float* w = &Ws[d * KP1_ * OUT_];  // rows d*4 .. d*4+3
        acc0 += z0 * w[0] + z1 * w[3] + z2 * w[6] + z3 * w[9];
        acc1 += z0 * w[1] + z1 * w[4] + z2 * w[7] + z3 * w[10];
        acc2 += z0 * w[2] + z1 * w[5] + z2 * w[8] + z3 * w[11];
    }

    // NaN guard (reference: where(isnan, 0))
    if (isnan(acc0)) acc0 = 0.0f;
    if (isnan(acc1)) acc1 = 0.0f;
    if (isnan(acc2)) acc2 = 0.0f;

    float* o = out + (size_t)(b * N_ + i) * OUT_;
    o[0] = acc0;
    o[1] = acc1;
    o[2] = acc2;
}

extern "C" void kernel_launch(void* const* d_in, const int* in_sizes, int n_in,
                              void* d_out, int out_size)
{
    // d_in[0] = As (ignored: reference overwrites it with J - I)
    const float* Xs = (const float*)d_in[1];
    const float* W  = (const float*)d_in[2];
    float* out      = (float*)d_out;

    reynolds_kernel<<<B_, N_>>>(Xs, W, out);
}

// round 4
// speedup vs baseline: 1.4265x; 1.4265x over previous
#include <cuda_runtime.h>

// Problem constants (fixed by the reference setup_inputs)
#define B_   8
#define N_   256
#define D_   16
#define KP1_ 4
#define REL_ 6
#define OUT_ 3
#define ROW_ (D_ * KP1_)   // 64 floats per (b, node)

// Inputs (metadata order): As (ignored), Xs (B,N,D,K+1) f32, W (64,3) f32
// Output: actions (B, N, 3) f32
//
// A = J - I (reference overwrites As), N=256:
//   L = J - 256 I,  L^2 = 65536 I - 256 J,  A^2 = 254 J + I
//   T_k[b,d] = sum_j Xs[b,j,d,k]
//   Zagg[b,i,d,0] = rel ? 0                          : X0
//   Zagg[b,i,d,1] = rel ? T1 - 256 X1                : T1 - X1
//   Zagg[b,i,d,2] = rel ? 256 X2 - T2 - 255 X1       : 254 T2 + X2
//   Zagg[b,i,d,3] = rel ? 256 T3 - 65536 X3 - 255 X1 : 64771 T3 - X3
//   actions = Zagg @ W, NaN -> 0

__global__ __launch_bounds__(N_) void reynolds_kernel(
    const float* __restrict__ Xs,   // (B, N, 64)
    const float* __restrict__ W,    // (64, 3)
    float* __restrict__ out)        // (B, N, 3)
{
    const int b   = blockIdx.x;
    const int tid = threadIdx.x;          // 0..255
    const int g   = tid >> 6;             // row-group 0..3 (64 rows each)
    const int l   = tid & 63;             // channel index 0..63 = (d*4 + k)

    __shared__ float Tp[4][ROW_];          // per-group partial column sums
    __shared__ float T[ROW_];              // final column sums
    __shared__ float Ws[ROW_ * OUT_];      // 192 floats

    if (tid < ROW_ * OUT_) Ws[tid] = W[tid];

    // ---- Phase 1: coalesced partial column sums (no shuffles, no atomics) ----
    // thread (g,l) sums Xs[b, g*64 + j, l] over j = 0..63.
    const float* base = Xs + ((size_t)(b * N_) + g * 64) * ROW_ + l;
    float a0 = 0.f, a1 = 0.f, a2 = 0.f, a3 = 0.f;
#pragma unroll
    for (int j = 0; j < 64; j += 4) {
        a0 += base[(j + 0) * ROW_];
        a1 += base[(j + 1) * ROW_];
        a2 += base[(j + 2) * ROW_];
        a3 += base[(j + 3) * ROW_];
    }
    Tp[g][l] = (a0 + a1) + (a2 + a3);
    __syncthreads();

    // ---- Phase 2: fold 4 partials ----
    if (tid < ROW_)
        T[tid] = (Tp[0][tid] + Tp[1][tid]) + (Tp[2][tid] + Tp[3][tid]);
    __syncthreads();

    // ---- Phase 3: per-node closed form + tiny GEMV (row is L1-hot) ----
    const float4* xrow = reinterpret_cast<const float4*>(
        Xs + ((size_t)(b * N_) + tid) * ROW_);

    const float Nf  = 256.0f;
    const float N2f = 65536.0f;
    const float Nm1 = 255.0f;
    const float Nm2 = 254.0f;
    const float C3  = 64771.0f;            // N^2 - 3N + 3

    float acc0 = 0.f, acc1 = 0.f, acc2 = 0.f;

#pragma unroll
    for (int d = 0; d < D_; d++) {
        const float4 x = xrow[d];
        const float t1 = T[d * 4 + 1];
        const float t2 = T[d * 4 + 2];
        const float t3 = T[d * 4 + 3];
        const bool rel = (d < REL_);

        const float z0 = rel ? 0.0f : x.x;
        const float z1 = rel ? (t1 - Nf * x.y)
                             : (t1 - x.y);
        const float z2 = rel ? (Nf * x.z - t2 - Nm1 * x.y)
                             : (Nm2 * t2 + x.z);
        const float z3 = rel ? (Nf * t3 - N2f * x.w - Nm1 * x.y)
                             : (C3 * t3 - x.w);

        const float* w = &Ws[d * KP1_ * OUT_];
        acc0 += z0 * w[0] + z1 * w[3] + z2 * w[6] + z3 * w[9];
        acc1 += z0 * w[1] + z1 * w[4] + z2 * w[7] + z3 * w[10];
        acc2 += z0 * w[2] + z1 * w[5] + z2 * w[8] + z3 * w[11];
    }

    // NaN guard (reference: where(isnan, 0))
    if (isnan(acc0)) acc0 = 0.0f;
    if (isnan(acc1)) acc1 = 0.0f;
    if (isnan(acc2)) acc2 = 0.0f;

    float* o = out + ((size_t)(b * N_) + tid) * OUT_;
    o[0] = acc0;
    o[1] = acc1;
    o[2] = acc2;
}

extern "C" void kernel_launch(void* const* d_in, const int* in_sizes, int n_in,
                              void* d_out, int out_size)
{
    // d_in[0] = As (ignored: reference overwrites it with J - I)
    const float* Xs = (const float*)d_in[1];
    const float* W  = (const float*)d_in[2];
    float* out      = (float*)d_out;

    reynolds_kernel<<<B_, N_>>>(Xs, W, out);
}

// round 6
// speedup vs baseline: 1.4686x; 1.0295x over previous
#include <cuda_runtime.h>

// Problem constants (fixed by the reference setup_inputs)
#define B_   8
#define N_   256
#define D_   16
#define KP1_ 4
#define REL_ 6
#define OUT_ 3
#define ROW_ (D_ * KP1_)   // 64 floats per (b, node)

// Inputs (metadata order): As (ignored), Xs (B,N,D,K+1) f32, W (64,3) f32
// Output: actions (B, N, 3) f32
//
// A = J - I (reference overwrites As), N=256:
//   L = J - 256 I,  L^2 = 65536 I - 256 J,  A^2 = 254 J + I
//   T_k[b,d] = sum_j Xs[b,j,d,k]
//   Zagg[b,i,d,0] = rel ? 0                          : X0
//   Zagg[b,i,d,1] = rel ? T1 - 256 X1                : T1 - X1
//   Zagg[b,i,d,2] = rel ? 256 X2 - T2 - 255 X1       : 254 T2 + X2
//   Zagg[b,i,d,3] = rel ? 256 T3 - 65536 X3 - 255 X1 : 64771 T3 - X3
//   actions = Zagg @ W, NaN -> 0

__global__ __launch_bounds__(N_, 1) void reynolds_kernel(
    const float* __restrict__ Xs,   // (B, N, 64)
    const float* __restrict__ W,    // (64, 3)
    float* __restrict__ out)        // (B, N, 3)
{
    const int b   = blockIdx.x;
    const int tid = threadIdx.x;          // 0..255
    const int c4  = tid & 15;             // float4 channel group (channels c4*4..c4*4+3)
    const int jg  = tid >> 4;             // row phase 0..15

    __shared__ float Sp[16][ROW_];        // partial column sums per row-phase
    __shared__ float T[ROW_];             // final column sums
    __shared__ float Ws[ROW_ * OUT_];     // 192 floats

    const float4* Xb = reinterpret_cast<const float4*>(Xs + (size_t)b * N_ * ROW_);

    // ---- Single load phase: 32 independent LDG.128, all batched up front ----
    // Column-sum inputs: rows jg + 16*s, channel group c4.
    float4 v[16];
#pragma unroll
    for (int s = 0; s < 16; s++)
        v[s] = Xb[(size_t)(jg + 16 * s) * (ROW_ / 4) + c4];

    // This thread's own node row (consumed register-resident in phase 3).
    float4 x[16];
    const float4* xr = Xb + (size_t)tid * (ROW_ / 4);
#pragma unroll
    for (int d = 0; d < D_; d++)
        x[d] = xr[d];

    if (tid < ROW_ * OUT_) Ws[tid] = W[tid];

    // ---- Tree-reduce the 16 row samples into one float4 partial ----
#pragma unroll
    for (int st = 8; st; st >>= 1)
#pragma unroll
        for (int s = 0; s < st; s++) {
            v[s].x += v[s + st].x;
            v[s].y += v[s + st].y;
            v[s].z += v[s + st].z;
            v[s].w += v[s + st].w;
        }
    reinterpret_cast<float4*>(&Sp[jg][0])[c4] = v[0];
    __syncthreads();

    // ---- Fold 16 partials (conflict-free: thread -> column) ----
    if (tid < ROW_) {
        float t = 0.f;
#pragma unroll
        for (int p = 0; p < 16; p++) t += Sp[p][tid];
        T[tid] = t;
    }
    __syncthreads();

    // ---- Phase 3: closed form + tiny GEMV, all operands in regs/shared ----
    const float Nf  = 256.0f;
    const float N2f = 65536.0f;
    const float Nm1 = 255.0f;
    const float Nm2 = 254.0f;
    const float C3  = 64771.0f;            // N^2 - 3N + 3

    float acc0 = 0.f, acc1 = 0.f, acc2 = 0.f;

#pragma unroll
    for (int d = 0; d < D_; d++) {
        const float t1 = T[d * 4 + 1];
        const float t2 = T[d * 4 + 2];
        const float t3 = T[d * 4 + 3];
        const bool rel = (d < REL_);

        const float z0 = rel ? 0.0f : x[d].x;
        const float z1 = rel ? (t1 - Nf * x[d].y)
                             : (t1 - x[d].y);
        const float z2 = rel ? (Nf * x[d].z - t2 - Nm1 * x[d].y)
                             : (Nm2 * t2 + x[d].z);
        const float z3 = rel ? (Nf * t3 - N2f * x[d].w - Nm1 * x[d].y)
                             : (C3 * t3 - x[d].w);

        const float* w = &Ws[d * KP1_ * OUT_];
        acc0 += z0 * w[0] + z1 * w[3] + z2 * w[6] + z3 * w[9];
        acc1 += z0 * w[1] + z1 * w[4] + z2 * w[7] + z3 * w[10];
        acc2 += z0 * w[2] + z1 * w[5] + z2 * w[8] + z3 * w[11];
    }

    // NaN guard (reference: where(isnan, 0))
    if (isnan(acc0)) acc0 = 0.0f;
    if (isnan(acc1)) acc1 = 0.0f;
    if (isnan(acc2)) acc2 = 0.0f;

    float* o = out + ((size_t)(b * N_) + tid) * OUT_;
    o[0] = acc0;
    o[1] = acc1;
    o[2] = acc2;
}

extern "C" void kernel_launch(void* const* d_in, const int* in_sizes, int n_in,
                              void* d_out, int out_size)
{
    // d_in[0] = As (ignored: reference overwrites it with J - I)
    const float* Xs = (const float*)d_in[1];
    const float* W  = (const float*)d_in[2];
    float* out      = (float*)d_out;

    reynolds_kernel<<<B_, N_>>>(Xs, W, out);
}